// round 9
// baseline (speedup 1.0000x reference)
#include <cuda_runtime.h>
#include <cuda_fp16.h>
#include <math.h>
#include <stdint.h>

// Problem constants
#define BATCH 8
#define CIN   192
#define HIMG  128
#define WIMG  128
#define HW    16384           // 128*128
#define MTOT  131072          // BATCH*HW
#define NQKV  576             // 3*C
#define NH    6
#define HD    32
#define WS    8
#define NWIN  64              // WS*WS
#define SCALE 0.17677669529663687f   // 32^-0.5

// ---------------- scratch (device globals; no runtime allocation) -----------
__device__ __align__(16) unsigned short d_xh [(size_t)MTOT * CIN];   // x^T fp16 [m][c]
__device__ __align__(16) unsigned short d_qkv[(size_t)MTOT * NQKV];  // fp16 [m][576]
__device__ __align__(16) unsigned short d_yb [(size_t)MTOT * CIN];   // fp16 [m][192]
__device__ __align__(16) unsigned short d_wfh[NQKV * CIN];           // fp16 [576][192]
__device__ __align__(16) unsigned short d_pwh[CIN * CIN];            // fp16 [192][192]
__device__ float d_bfused[NQKV];
__device__ float d_biasT[NH * NWIN * NWIN];      // [head][n][m]

// ---------------- helpers ----------------------------------------------------
__device__ __forceinline__ void mma_f16(float c[4], const uint32_t a[4], const uint32_t b[2]) {
    asm volatile(
        "mma.sync.aligned.m16n8k16.row.col.f32.f16.f16.f32 "
        "{%0,%1,%2,%3}, {%4,%5,%6,%7}, {%8,%9}, {%0,%1,%2,%3};"
        : "+f"(c[0]), "+f"(c[1]), "+f"(c[2]), "+f"(c[3])
        : "r"(a[0]), "r"(a[1]), "r"(a[2]), "r"(a[3]), "r"(b[0]), "r"(b[1]));
}
__device__ __forceinline__ uint32_t pack2(float a, float b) {
    __half2 h = __floats2half2_rn(a, b);
    return *reinterpret_cast<uint32_t*>(&h);
}
__device__ __forceinline__ void cp16(uint32_t saddr, const void* g) {
    asm volatile("cp.async.cg.shared.global [%0], [%1], 16;" :: "r"(saddr), "l"(g));
}
#define CP_COMMIT() asm volatile("cp.async.commit_group;")
#define CP_WAIT1()  asm volatile("cp.async.wait_group 1;")

// ---------------- kernel 1: weight prep (fuse + fp16 convert) ---------------
__global__ void prep_w(const float* __restrict__ QK_w, const float* __restrict__ QK_b,
                       const float* __restrict__ V_w,  const float* __restrict__ V_b,
                       const float* __restrict__ pw) {
    int idx = blockIdx.x * 256 + threadIdx.x;
    if (idx < NQKV * CIN) {
        int n = idx / CIN, k = idx - n * CIN;
        float v = (n < 2 * CIN) ? QK_w[n * CIN + k] : V_w[(n - 2 * CIN) * CIN + k];
        d_wfh[idx] = __half_as_ushort(__float2half(v));
    }
    if (idx < CIN * CIN)
        d_pwh[idx] = __half_as_ushort(__float2half(pw[idx]));
    if (idx < NQKV)
        d_bfused[idx] = (idx < 2 * CIN) ? QK_b[idx] : V_b[idx - 2 * CIN];
}

// ---------------- kernel 2: relative-position bias via meta MLP -------------
__global__ void bias_kernel(const float* __restrict__ w1, const float* __restrict__ b1,
                            const float* __restrict__ w2, const float* __restrict__ b2) {
    int idx = blockIdx.x * 256 + threadIdx.x;   // 0..4095
    if (idx >= NWIN * NWIN) return;
    int n1 = idx >> 6, n2 = idx & 63;
    float di = (float)((n1 >> 3) - (n2 >> 3));
    float dj = (float)((n1 & 7) - (n2 & 7));
    float s0 = (di > 0.f) ? 1.f : ((di < 0.f) ? -1.f : 0.f);
    float s1 = (dj > 0.f) ? 1.f : ((dj < 0.f) ? -1.f : 0.f);
    float rp0 = s0 * log1pf(fabsf(di));
    float rp1 = s1 * log1pf(fabsf(dj));
    float acc[NH];
#pragma unroll
    for (int c = 0; c < NH; c++) acc[c] = b2[c];
    for (int t = 0; t < 256; t++) {
        float h = rp0 * w1[t] + rp1 * w1[256 + t] + b1[t];
        h = fmaxf(h, 0.f);
#pragma unroll
        for (int c = 0; c < NH; c++) acc[c] += h * w2[t * NH + c];
    }
#pragma unroll
    for (int c = 0; c < NH; c++)
        d_biasT[(c * NWIN + n1) * NWIN + n2] = acc[c];
}

// ---------------- kernel 3: transpose+convert x -> d_xh fp16 [m][c] ---------
__global__ void __launch_bounds__(256) transpose_x(const float* __restrict__ x) {
    __shared__ float tile[32][33];
    int cb = blockIdx.x << 5;
    int mb = blockIdx.y << 5;
    int b  = mb >> 14;
    int hw0 = mb & (HW - 1);
    int tx = threadIdx.x & 31, ty = threadIdx.x >> 5;
    const float* src = x + (size_t)b * CIN * HW + hw0;
#pragma unroll
    for (int i = 0; i < 4; i++)
        tile[ty + i * 8][tx] = src[(size_t)(cb + ty + i * 8) * HW + tx];
    __syncthreads();
#pragma unroll
    for (int i = 0; i < 4; i++) {
        int m = mb + ty + i * 8;
        d_xh[(size_t)m * CIN + cb + tx] =
            __half_as_ushort(__float2half(tile[tx][ty + i * 8]));
    }
}

// ---------------- GEMM common geometry ---------------------------------------
// fp16 m16n8k16, tiles 128x64, BK=32 halves (=16 half2 words), 2-stage cp.async
// smem rows: 16 data words + 4 pad = 20 words (banks 20*lr+lc bijective)
#define G_SS 20
#define G_SA_WORDS (128 * G_SS)      // 2560 words per stage
#define G_SB_WORDS (64 * G_SS)       // 1280 words per stage
#define G_STAGE_WORDS (G_SA_WORDS + G_SB_WORDS)   // 3840

// ---------------- kernel 4: GEMM1 qkv = xh @ wfh^T + b ----------------------
__global__ void __launch_bounds__(256, 4) gemm_qkv_tc() {
    __shared__ __align__(16) uint32_t sh[2 * G_STAGE_WORDS];   // 30.7 KB
    uint32_t sh_s = (uint32_t)__cvta_generic_to_shared(sh);

    int m0 = blockIdx.y * 128;
    int n0 = blockIdx.x * 64;
    int t = threadIdx.x;
    int lane = t & 31, warp = t >> 5;
    int wm = (warp >> 1) << 5, wn = (warp & 1) << 5;
    int lr = lane >> 2, lc = lane & 3;

    // A: 2 chunks/thread; chunk idx c: m=c>>2, kh=(c&3)*8 halves
    int a_m0 = t >> 2,         a_h0 = (t & 3) << 3;
    int a_m1 = (t + 256) >> 2, a_h1 = a_h0;
    int b_n = t >> 2,          b_h = (t & 3) << 3;

    float c[2][4][4];
#pragma unroll
    for (int i = 0; i < 2; i++)
#pragma unroll
        for (int j = 0; j < 4; j++)
#pragma unroll
            for (int q = 0; q < 4; q++) c[i][j][q] = 0.f;

#define G1L(stg, k0) do {                                                          \
        uint32_t dA = sh_s + ((stg) * G_STAGE_WORDS) * 4;                          \
        cp16(dA + (a_m0 * G_SS + (a_h0 >> 1)) * 4, d_xh + (size_t)(m0 + a_m0) * CIN + (k0) + a_h0); \
        cp16(dA + (a_m1 * G_SS + (a_h1 >> 1)) * 4, d_xh + (size_t)(m0 + a_m1) * CIN + (k0) + a_h1); \
        uint32_t dB = dA + G_SA_WORDS * 4;                                         \
        cp16(dB + (b_n * G_SS + (b_h >> 1)) * 4, d_wfh + (size_t)(n0 + b_n) * CIN + (k0) + b_h); \
    } while (0)

    G1L(0, 0);  CP_COMMIT();

    for (int it = 0; it < 6; it++) {
        if (it + 1 < 6) { G1L((it + 1) & 1, (it + 1) * 32); }
        CP_COMMIT();
        CP_WAIT1();           // stage it resident (only just-issued group pending)
        __syncthreads();
        const uint32_t* sA = sh + (it & 1) * G_STAGE_WORDS;
        const uint32_t* sB = sA + G_SA_WORDS;
#pragma unroll
        for (int ks = 0; ks < 2; ks++) {
            int kb = ks * 8;
            uint32_t a[2][4], bfr[4][2];
#pragma unroll
            for (int i = 0; i < 2; i++) {
                int row = wm + i * 16 + lr;
                a[i][0] = sA[row * G_SS + kb + lc];
                a[i][1] = sA[(row + 8) * G_SS + kb + lc];
                a[i][2] = sA[row * G_SS + kb + lc + 4];
                a[i][3] = sA[(row + 8) * G_SS + kb + lc + 4];
            }
#pragma unroll
            for (int j = 0; j < 4; j++) {
                int col = wn + j * 8 + lr;
                bfr[j][0] = sB[col * G_SS + kb + lc];
                bfr[j][1] = sB[col * G_SS + kb + lc + 4];
            }
#pragma unroll
            for (int i = 0; i < 2; i++)
#pragma unroll
                for (int j = 0; j < 4; j++)
                    mma_f16(c[i][j], a[i], bfr[j]);
        }
        __syncthreads();      // protect stage (it) buffer before it is overwritten
    }

#pragma unroll
    for (int i = 0; i < 2; i++) {
        int row0 = m0 + wm + i * 16 + lr;
#pragma unroll
        for (int j = 0; j < 4; j++) {
            int col = n0 + wn + j * 8 + (lc << 1);
            float b0 = d_bfused[col], b1 = d_bfused[col + 1];
            *(uint32_t*)&d_qkv[(size_t)row0 * NQKV + col] = pack2(c[i][j][0] + b0, c[i][j][1] + b1);
            *(uint32_t*)&d_qkv[(size_t)(row0 + 8) * NQKV + col] = pack2(c[i][j][2] + b0, c[i][j][3] + b1);
        }
    }
}

// ---------------- kernel 5: attention (fp16 mma) -----------------------------
// smem (float words):
//   [0,4352)     qs[32][68], ks[32][68] fp32    -> reused as pnm16 [64][36w]
//   [4352,5504)  vdm16 [d=32][36w] (72 halves: m-major within row)
//   [5504,6784)  vmd16 [m=64][20w] (40 halves: d)
//   [6784,8064)  ond16 [n=64][20w]
//   [8064,8192)  rmaxP[64][2]
//   [8192,8320)  rsumP[64][2]
#define AT_QS   0
#define AT_KS   2176
#define AT_PNM  0
#define AT_VDM  4352
#define AT_VMD  5504
#define AT_OND  6784
#define AT_RMX  8064
#define AT_RSM  8192
#define AT_TOT  8320
__global__ void __launch_bounds__(256) attn_tc_kernel() {
    __shared__ __align__(16) float sh[AT_TOT];
    float* qs = sh + AT_QS;
    float* ks = sh + AT_KS;
    uint32_t* pnm16 = (uint32_t*)(sh + AT_PNM);          // [n][36 words]
    uint32_t* vdm16 = (uint32_t*)(sh + AT_VDM);          // [d][36 words]
    unsigned short* vdm16h = (unsigned short*)vdm16;     // [d][72 halves]
    uint32_t* vmd16 = (uint32_t*)(sh + AT_VMD);          // [m][20 words]
    uint32_t* ond16 = (uint32_t*)(sh + AT_OND);          // [n][20 words]
    unsigned short* ond16h = (unsigned short*)ond16;     // [n][40 halves]
    float* rmaxP = sh + AT_RMX;
    float* rsumP = sh + AT_RSM;

    int w_   = blockIdx.x;
    int head = blockIdx.y;
    int t = threadIdx.x;

    int b   = w_ >> 8;
    int rem = w_ & 255;
    int wi  = rem >> 4, wj = rem & 15;
    int base_pix = b * HW + wi * 8 * WIMG + wj * 8;
    int chq = head * HD;

    // ---- phase 1: load q,k,v (fp16 global) ----
#pragma unroll
    for (int r = 0; r < 2; r++) {
        int idx = t + r * 256;             // 0..511
        int n  = idx >> 3;
        int dq = (idx & 7) << 2;           // 0,4,...,28
        int m = base_pix + ((n >> 3) * WIMG) + (n & 7);
        const unsigned short* p = d_qkv + (size_t)m * NQKV + chq + dq;
        uint2 qraw = *(const uint2*)p;
        uint2 kraw = *(const uint2*)(p + CIN);
        uint2 vraw = *(const uint2*)(p + 2 * CIN);
        float2 q01 = __half22float2(*reinterpret_cast<__half2*>(&qraw.x));
        float2 q23 = __half22float2(*reinterpret_cast<__half2*>(&qraw.y));
        float2 k01 = __half22float2(*reinterpret_cast<__half2*>(&kraw.x));
        float2 k23 = __half22float2(*reinterpret_cast<__half2*>(&kraw.y));
        qs[(dq + 0) * 68 + n] = q01.x * SCALE; qs[(dq + 1) * 68 + n] = q01.y * SCALE;
        qs[(dq + 2) * 68 + n] = q23.x * SCALE; qs[(dq + 3) * 68 + n] = q23.y * SCALE;
        ks[(dq + 0) * 68 + n] = k01.x; ks[(dq + 1) * 68 + n] = k01.y;
        ks[(dq + 2) * 68 + n] = k23.x; ks[(dq + 3) * 68 + n] = k23.y;
        // v d-major halves
        const unsigned short* vh = (const unsigned short*)&vraw;
        vdm16h[(dq + 0) * 72 + n] = vh[0];
        vdm16h[(dq + 1) * 72 + n] = vh[1];
        vdm16h[(dq + 2) * 72 + n] = vh[2];
        vdm16h[(dq + 3) * 72 + n] = vh[3];
        // v m-major words (d pairs) — raw copy
        vmd16[n * 20 + (dq >> 1)]     = vraw.x;
        vmd16[n * 20 + (dq >> 1) + 1] = vraw.y;
    }
    __syncthreads();

    // ---- phase 2: 8x8 circular conv per channel (fp32) ----
    {
        int ci = t & 7;
        int d  = t >> 3;
        const float4* qrow = (const float4*)(qs + d * 68);
        const float4* krow = (const float4*)(ks + d * 68);
        float oacc[8];
#pragma unroll
        for (int j = 0; j < 8; j++) oacc[j] = 0.f;
#pragma unroll
        for (int ai = 0; ai < 8; ai++) {
            int ki = (ci - ai) & 7;
            float4 k0 = krow[ki * 2], k1 = krow[ki * 2 + 1];
            float kr[8] = {k0.x, k0.y, k0.z, k0.w, k1.x, k1.y, k1.z, k1.w};
            float4 q0 = qrow[ai * 2], q1 = qrow[ai * 2 + 1];
            float qv[8] = {q0.x, q0.y, q0.z, q0.w, q1.x, q1.y, q1.z, q1.w};
#pragma unroll
            for (int aj = 0; aj < 8; aj++) {
#pragma unroll
                for (int j = 0; j < 8; j++) oacc[j] += qv[aj] * kr[(j - aj) & 7];
            }
        }
#pragma unroll
        for (int j = 0; j < 8; j++)
            ond16h[(ci * 8 + j) * 40 + d] = __half_as_ushort(__float2half(oacc[j]));
    }
    __syncthreads();

    // ---- phase 3: logits s = o @ v^T + bias (fp16 mma, K=32 = 2 ksteps) ----
    int lane = t & 31, w = t >> 5;
    int wr = w >> 1, wc = w & 1;      // 4x2 warp grid
    int n0w = wr * 16;
    int lr = lane >> 2, lc = lane & 3;

    uint32_t afr[2][4];
#pragma unroll
    for (int ksv = 0; ksv < 2; ksv++) {
        int kb = ksv * 8;
        afr[ksv][0] = ond16[(n0w + lr) * 20 + kb + lc];
        afr[ksv][1] = ond16[(n0w + lr + 8) * 20 + kb + lc];
        afr[ksv][2] = ond16[(n0w + lr) * 20 + kb + lc + 4];
        afr[ksv][3] = ond16[(n0w + lr + 8) * 20 + kb + lc + 4];
    }
    int m0w = wc * 32;
    float sacc[4][4];
#pragma unroll
    for (int mt = 0; mt < 4; mt++)
#pragma unroll
        for (int q = 0; q < 4; q++) sacc[mt][q] = 0.f;
#pragma unroll
    for (int mt = 0; mt < 4; mt++) {
        int mrow = m0w + mt * 8 + lr;
#pragma unroll
        for (int ksv = 0; ksv < 2; ksv++) {
            int kb = ksv * 8;
            uint32_t bf[2] = {vmd16[mrow * 20 + kb + lc], vmd16[mrow * 20 + kb + lc + 4]};
            mma_f16(sacc[mt], afr[ksv], bf);
        }
    }
    // bias add
    {
        const float* bp = d_biasT + head * NWIN * NWIN;
#pragma unroll
        for (int mt = 0; mt < 4; mt++) {
            int col = m0w + mt * 8 + (lc << 1);
            float2 b0 = *(const float2*)(bp + (n0w + lr) * NWIN + col);
            float2 b1 = *(const float2*)(bp + (n0w + lr + 8) * NWIN + col);
            sacc[mt][0] += b0.x; sacc[mt][1] += b0.y;
            sacc[mt][2] += b1.x; sacc[mt][3] += b1.y;
        }
    }
    // softmax (2-warp combine over m)
    float mx0 = -1e30f, mx1 = -1e30f;
#pragma unroll
    for (int mt = 0; mt < 4; mt++) {
        mx0 = fmaxf(mx0, fmaxf(sacc[mt][0], sacc[mt][1]));
        mx1 = fmaxf(mx1, fmaxf(sacc[mt][2], sacc[mt][3]));
    }
    mx0 = fmaxf(mx0, __shfl_xor_sync(0xffffffffu, mx0, 1));
    mx0 = fmaxf(mx0, __shfl_xor_sync(0xffffffffu, mx0, 2));
    mx1 = fmaxf(mx1, __shfl_xor_sync(0xffffffffu, mx1, 1));
    mx1 = fmaxf(mx1, __shfl_xor_sync(0xffffffffu, mx1, 2));
    if (lc == 0) {
        rmaxP[(n0w + lr) * 2 + wc]     = mx0;
        rmaxP[(n0w + lr + 8) * 2 + wc] = mx1;
    }
    __syncthreads();
    float g0 = fmaxf(rmaxP[(n0w + lr) * 2],     rmaxP[(n0w + lr) * 2 + 1]);
    float g1 = fmaxf(rmaxP[(n0w + lr + 8) * 2], rmaxP[(n0w + lr + 8) * 2 + 1]);
    float s0 = 0.f, s1 = 0.f;
#pragma unroll
    for (int mt = 0; mt < 4; mt++) {
        float e0 = __expf(sacc[mt][0] - g0);
        float e1 = __expf(sacc[mt][1] - g0);
        float e2 = __expf(sacc[mt][2] - g1);
        float e3 = __expf(sacc[mt][3] - g1);
        s0 += e0 + e1; s1 += e2 + e3;
        int colw = wc * 16 + mt * 4 + lc;   // word index of m-pair
        pnm16[(n0w + lr) * 36 + colw]     = pack2(e0, e1);
        pnm16[(n0w + lr + 8) * 36 + colw] = pack2(e2, e3);
    }
    s0 += __shfl_xor_sync(0xffffffffu, s0, 1);
    s0 += __shfl_xor_sync(0xffffffffu, s0, 2);
    s1 += __shfl_xor_sync(0xffffffffu, s1, 1);
    s1 += __shfl_xor_sync(0xffffffffu, s1, 2);
    if (lc == 0) {
        rsumP[(n0w + lr) * 2 + wc]     = s0;
        rsumP[(n0w + lr + 8) * 2 + wc] = s1;
    }
    __syncthreads();

    // ---- phase 5: y = p @ v (fp16 mma, K=64 = 4 ksteps), normalize, store ---
    int d0w = wc * 16;
    float yacc[2][4];
#pragma unroll
    for (int dt = 0; dt < 2; dt++)
#pragma unroll
        for (int q = 0; q < 4; q++) yacc[dt][q] = 0.f;
#pragma unroll
    for (int st = 0; st < 4; st++) {
        int kb = st * 8;
        uint32_t a[4] = {
            pnm16[(n0w + lr) * 36 + kb + lc],
            pnm16[(n0w + lr + 8) * 36 + kb + lc],
            pnm16[(n0w + lr) * 36 + kb + lc + 4],
            pnm16[(n0w + lr + 8) * 36 + kb + lc + 4]};
#pragma unroll
        for (int dt = 0; dt < 2; dt++) {
            int dcol = d0w + dt * 8 + lr;
            uint32_t bf[2] = {vdm16[dcol * 36 + kb + lc], vdm16[dcol * 36 + kb + lc + 4]};
            mma_f16(yacc[dt], a, bf);
        }
    }
    {
        int r0 = n0w + lr, r1 = r0 + 8;
        float ri0 = 1.f / (rsumP[2 * r0] + rsumP[2 * r0 + 1]);
        float ri1 = 1.f / (rsumP[2 * r1] + rsumP[2 * r1 + 1]);
        int p0 = base_pix + ((r0 >> 3) * WIMG) + (r0 & 7);
        int p1 = base_pix + ((r1 >> 3) * WIMG) + (r1 & 7);
#pragma unroll
        for (int dt = 0; dt < 2; dt++) {
            int dc = chq + d0w + dt * 8 + (lc << 1);
            *(uint32_t*)&d_yb[(size_t)p0 * CIN + dc] = pack2(yacc[dt][0] * ri0, yacc[dt][1] * ri0);
            *(uint32_t*)&d_yb[(size_t)p1 * CIN + dc] = pack2(yacc[dt][2] * ri1, yacc[dt][3] * ri1);
        }
    }
}

// ---------------- kernel 6: GEMM2 out = yb @ pwh^T + pb ---------------------
#define G2_SH_WORDS 8448   // >= max(2*G_STAGE_WORDS=7680, Cs 128*65=8320)
__global__ void __launch_bounds__(256, 4) gemm_proj_tc(const float* __restrict__ pb,
                                                       float* __restrict__ out) {
    __shared__ __align__(16) uint32_t sh[G2_SH_WORDS];   // 33.8 KB
    uint32_t sh_s = (uint32_t)__cvta_generic_to_shared(sh);

    int m0 = blockIdx.y * 128;
    int n0 = blockIdx.x * 64;
    int b  = m0 >> 14;
    int hw0 = m0 & (HW - 1);

    int t = threadIdx.x;
    int lane = t & 31, warp = t >> 5;
    int wm = (warp >> 1) << 5, wn = (warp & 1) << 5;
    int lr = lane >> 2, lc = lane & 3;

    int a_m0 = t >> 2,         a_h0 = (t & 3) << 3;
    int a_m1 = (t + 256) >> 2, a_h1 = a_h0;
    int b_n = t >> 2,          b_h = (t & 3) << 3;

    float c[2][4][4];
#pragma unroll
    for (int i = 0; i < 2; i++)
#pragma unroll
        for (int j = 0; j < 4; j++)
#pragma unroll
            for (int q = 0; q < 4; q++) c[i][j][q] = 0.f;

#define G2L(stg, k0) do {                                                          \
        uint32_t dA = sh_s + ((stg) * G_STAGE_WORDS) * 4;                          \
        cp16(dA + (a_m0 * G_SS + (a_h0 >> 1)) * 4, d_yb + (size_t)(m0 + a_m0) * CIN + (k0) + a_h0); \
        cp16(dA + (a_m1 * G_SS + (a_h1 >> 1)) * 4, d_yb + (size_t)(m0 + a_m1) * CIN + (k0) + a_h1); \
        uint32_t dB = dA + G_SA_WORDS * 4;                                         \
        cp16(dB + (b_n * G_SS + (b_h >> 1)) * 4, d_pwh + (size_t)(n0 + b_n) * CIN + (k0) + b_h); \
    } while (0)

    G2L(0, 0);  CP_COMMIT();

    for (int it = 0; it < 6; it++) {
        if (it + 1 < 6) { G2L((it + 1) & 1, (it + 1) * 32); }
        CP_COMMIT();
        CP_WAIT1();
        __syncthreads();
        const uint32_t* sA = sh + (it & 1) * G_STAGE_WORDS;
        const uint32_t* sB = sA + G_SA_WORDS;
#pragma unroll
        for (int ks = 0; ks < 2; ks++) {
            int kb = ks * 8;
            uint32_t a[2][4], bfr[4][2];
#pragma unroll
            for (int i = 0; i < 2; i++) {
                int row = wm + i * 16 + lr;
                a[i][0] = sA[row * G_SS + kb + lc];
                a[i][1] = sA[(row + 8) * G_SS + kb + lc];
                a[i][2] = sA[row * G_SS + kb + lc + 4];
                a[i][3] = sA[(row + 8) * G_SS + kb + lc + 4];
            }
#pragma unroll
            for (int j = 0; j < 4; j++) {
                int col = wn + j * 8 + lr;
                bfr[j][0] = sB[col * G_SS + kb + lc];
                bfr[j][1] = sB[col * G_SS + kb + lc + 4];
            }
#pragma unroll
            for (int i = 0; i < 2; i++)
#pragma unroll
                for (int j = 0; j < 4; j++)
                    mma_f16(c[i][j], a[i], bfr[j]);
        }
        __syncthreads();
    }

    // stage C in smem for coalesced transposed output
    float* Cs = (float*)sh;   // [128][65] = 8320 words <= G2_SH_WORDS
#pragma unroll
    for (int i = 0; i < 2; i++) {
        int row = wm + i * 16 + lr;
#pragma unroll
        for (int j = 0; j < 4; j++) {
            int col = wn + j * 8 + (lc << 1);
            Cs[row * 65 + col]           = c[i][j][0];
            Cs[row * 65 + col + 1]       = c[i][j][1];
            Cs[(row + 8) * 65 + col]     = c[i][j][2];
            Cs[(row + 8) * 65 + col + 1] = c[i][j][3];
        }
    }
    __syncthreads();

    int mL = t & 127;
    int nh = (t >> 7) << 5;
    for (int nn = 0; nn < 32; nn++) {
        int n = nh + nn;
        out[(size_t)(b * CIN + n0 + n) * HW + hw0 + mL] = Cs[mL * 65 + n] + pb[n0 + n];
    }
}

// ---------------- launch -----------------------------------------------------
extern "C" void kernel_launch(void* const* d_in, const int* in_sizes, int n_in,
                              void* d_out, int out_size) {
    const float* x      = (const float*)d_in[0];
    const float* V_w    = (const float*)d_in[1];
    const float* V_b    = (const float*)d_in[2];
    const float* QK_w   = (const float*)d_in[3];
    const float* QK_b   = (const float*)d_in[4];
    const float* proj_w = (const float*)d_in[5];
    const float* proj_b = (const float*)d_in[6];
    const float* mw1    = (const float*)d_in[7];
    const float* mb1    = (const float*)d_in[8];
    const float* mw2    = (const float*)d_in[9];
    const float* mb2    = (const float*)d_in[10];
    float* out = (float*)d_out;

    prep_w<<<(NQKV * CIN + 255) / 256, 256>>>(QK_w, QK_b, V_w, V_b, proj_w);
    bias_kernel<<<(NWIN * NWIN + 255) / 256, 256>>>(mw1, mb1, mw2, mb2);
    transpose_x<<<dim3(CIN / 32, MTOT / 32), 256>>>(x);
    gemm_qkv_tc<<<dim3(NQKV / 64, MTOT / 128), 256>>>();
    attn_tc_kernel<<<dim3(2048, NH), 256>>>();
    gemm_proj_tc<<<dim3(CIN / 64, MTOT / 128), 256>>>(proj_b, out);
}

// round 11
// speedup vs baseline: 1.0855x; 1.0855x over previous
#include <cuda_runtime.h>
#include <cuda_fp16.h>
#include <math.h>
#include <stdint.h>

// Problem constants
#define BATCH 8
#define CIN   192
#define HIMG  128
#define WIMG  128
#define HW    16384           // 128*128
#define MTOT  131072          // BATCH*HW
#define NQKV  576             // 3*C
#define NH    6
#define HD    32
#define WS    8
#define NWIN  64              // WS*WS
#define SCALE 0.17677669529663687f   // 32^-0.5

// ---------------- scratch (device globals; no runtime allocation) -----------
__device__ __align__(16) unsigned short d_xh [(size_t)MTOT * CIN];   // x^T fp16 [m][c]
__device__ __align__(16) unsigned short d_qkv[(size_t)MTOT * NQKV];  // fp16 [m][576]
__device__ __align__(16) unsigned short d_yb [(size_t)MTOT * CIN];   // fp16 [m][192]
__device__ __align__(16) unsigned short d_wfh[NQKV * CIN];           // fp16 [576][192]
__device__ __align__(16) unsigned short d_pwh[CIN * CIN];            // fp16 [192][192]
__device__ float d_bfused[NQKV];
__device__ float d_biasT[NH * NWIN * NWIN];      // [head][n][m]

// ---------------- helpers ----------------------------------------------------
__device__ __forceinline__ void mma_f16(float c[4], const uint32_t a[4], const uint32_t b[2]) {
    asm volatile(
        "mma.sync.aligned.m16n8k16.row.col.f32.f16.f16.f32 "
        "{%0,%1,%2,%3}, {%4,%5,%6,%7}, {%8,%9}, {%0,%1,%2,%3};"
        : "+f"(c[0]), "+f"(c[1]), "+f"(c[2]), "+f"(c[3])
        : "r"(a[0]), "r"(a[1]), "r"(a[2]), "r"(a[3]), "r"(b[0]), "r"(b[1]));
}
__device__ __forceinline__ uint32_t pack2(float a, float b) {
    __half2 h = __floats2half2_rn(a, b);
    return *reinterpret_cast<uint32_t*>(&h);
}
__device__ __forceinline__ void fma2(unsigned long long& acc, unsigned long long a,
                                     unsigned long long b) {
    asm("fma.rn.f32x2 %0, %1, %2, %0;" : "+l"(acc) : "l"(a), "l"(b));
}
__device__ __forceinline__ void cp16(uint32_t saddr, const void* g) {
    asm volatile("cp.async.cg.shared.global [%0], [%1], 16;" :: "r"(saddr), "l"(g));
}
#define CP_COMMIT() asm volatile("cp.async.commit_group;")
#define CP_WAIT1()  asm volatile("cp.async.wait_group 1;")

// ---------------- kernel 1: weight prep (fuse + fp16 convert) ---------------
__global__ void prep_w(const float* __restrict__ QK_w, const float* __restrict__ QK_b,
                       const float* __restrict__ V_w,  const float* __restrict__ V_b,
                       const float* __restrict__ pw) {
    int idx = blockIdx.x * 256 + threadIdx.x;
    if (idx < NQKV * CIN) {
        int n = idx / CIN, k = idx - n * CIN;
        float v = (n < 2 * CIN) ? QK_w[n * CIN + k] : V_w[(n - 2 * CIN) * CIN + k];
        d_wfh[idx] = __half_as_ushort(__float2half(v));
    }
    if (idx < CIN * CIN)
        d_pwh[idx] = __half_as_ushort(__float2half(pw[idx]));
    if (idx < NQKV)
        d_bfused[idx] = (idx < 2 * CIN) ? QK_b[idx] : V_b[idx - 2 * CIN];
}

// ---------------- kernel 2: relative-position bias via meta MLP -------------
__global__ void bias_kernel(const float* __restrict__ w1, const float* __restrict__ b1,
                            const float* __restrict__ w2, const float* __restrict__ b2) {
    int idx = blockIdx.x * 256 + threadIdx.x;   // 0..4095
    if (idx >= NWIN * NWIN) return;
    int n1 = idx >> 6, n2 = idx & 63;
    float di = (float)((n1 >> 3) - (n2 >> 3));
    float dj = (float)((n1 & 7) - (n2 & 7));
    float s0 = (di > 0.f) ? 1.f : ((di < 0.f) ? -1.f : 0.f);
    float s1 = (dj > 0.f) ? 1.f : ((dj < 0.f) ? -1.f : 0.f);
    float rp0 = s0 * log1pf(fabsf(di));
    float rp1 = s1 * log1pf(fabsf(dj));
    float acc[NH];
#pragma unroll
    for (int c = 0; c < NH; c++) acc[c] = b2[c];
    for (int t = 0; t < 256; t++) {
        float h = rp0 * w1[t] + rp1 * w1[256 + t] + b1[t];
        h = fmaxf(h, 0.f);
#pragma unroll
        for (int c = 0; c < NH; c++) acc[c] += h * w2[t * NH + c];
    }
#pragma unroll
    for (int c = 0; c < NH; c++)
        d_biasT[(c * NWIN + n1) * NWIN + n2] = acc[c];
}

// ---------------- kernel 3: transpose+convert x -> d_xh fp16 [m][c] ---------
__global__ void __launch_bounds__(256) transpose_x(const float* __restrict__ x) {
    __shared__ float tile[32][33];
    int cb = blockIdx.x << 5;
    int mb = blockIdx.y << 5;
    int b  = mb >> 14;
    int hw0 = mb & (HW - 1);
    int tx = threadIdx.x & 31, ty = threadIdx.x >> 5;
    const float* src = x + (size_t)b * CIN * HW + hw0;
#pragma unroll
    for (int i = 0; i < 4; i++)
        tile[ty + i * 8][tx] = src[(size_t)(cb + ty + i * 8) * HW + tx];
    __syncthreads();
#pragma unroll
    for (int i = 0; i < 4; i++) {
        int m = mb + ty + i * 8;
        d_xh[(size_t)m * CIN + cb + tx] =
            __half_as_ushort(__float2half(tile[tx][ty + i * 8]));
    }
}

// ---------------- GEMM common geometry ---------------------------------------
// fp16 m16n8k16, tiles 128x64, BK=32 halves (=16 half2 words), 3-stage cp.async
#define G_SS 20
#define G_SA_WORDS (128 * G_SS)      // 2560 words per stage
#define G_SB_WORDS (64 * G_SS)       // 1280 words per stage

// ---------------- kernel 4: GEMM1 qkv = xh @ wfh^T + b ----------------------
__global__ void __launch_bounds__(256) gemm_qkv_tc() {
    __shared__ __align__(16) uint32_t sh[3 * G_SA_WORDS + 3 * G_SB_WORDS];  // 45 KB
    uint32_t* sAb = sh;
    uint32_t* sBb = sh + 3 * G_SA_WORDS;
    uint32_t sA_s = (uint32_t)__cvta_generic_to_shared(sAb);
    uint32_t sB_s = (uint32_t)__cvta_generic_to_shared(sBb);

    int m0 = blockIdx.y * 128;
    int n0 = blockIdx.x * 64;
    int t = threadIdx.x;
    int lane = t & 31, warp = t >> 5;
    int wm = (warp >> 1) << 5, wn = (warp & 1) << 5;
    int lr = lane >> 2, lc = lane & 3;

    int a_m0 = t >> 2,         a_h0 = (t & 3) << 3;
    int a_m1 = (t + 256) >> 2, a_h1 = a_h0;
    int b_n = t >> 2,          b_h = (t & 3) << 3;

    float c[2][4][4];
#pragma unroll
    for (int i = 0; i < 2; i++)
#pragma unroll
        for (int j = 0; j < 4; j++)
#pragma unroll
            for (int q = 0; q < 4; q++) c[i][j][q] = 0.f;

#define G1L(stg, k0) do {                                                          \
        uint32_t dA = sA_s + ((stg) * G_SA_WORDS) * 4;                             \
        cp16(dA + (a_m0 * G_SS + (a_h0 >> 1)) * 4, d_xh + (size_t)(m0 + a_m0) * CIN + (k0) + a_h0); \
        cp16(dA + (a_m1 * G_SS + (a_h1 >> 1)) * 4, d_xh + (size_t)(m0 + a_m1) * CIN + (k0) + a_h1); \
        uint32_t dB = sB_s + ((stg) * G_SB_WORDS) * 4;                             \
        cp16(dB + (b_n * G_SS + (b_h >> 1)) * 4, d_wfh + (size_t)(n0 + b_n) * CIN + (k0) + b_h); \
    } while (0)

    G1L(0, 0);  CP_COMMIT();
    G1L(1, 32); CP_COMMIT();

    for (int it = 0; it < 6; it++) {
        CP_WAIT1();
        __syncthreads();
        int k0n = (it + 2) * 32;
        if (k0n < CIN) { G1L((it + 2) % 3, k0n); }
        CP_COMMIT();
        const uint32_t* sA = sAb + (it % 3) * G_SA_WORDS;
        const uint32_t* sB = sBb + (it % 3) * G_SB_WORDS;
#pragma unroll
        for (int ks = 0; ks < 2; ks++) {
            int kb = ks * 8;
            uint32_t a[2][4], bfr[4][2];
#pragma unroll
            for (int i = 0; i < 2; i++) {
                int row = wm + i * 16 + lr;
                a[i][0] = sA[row * G_SS + kb + lc];
                a[i][1] = sA[(row + 8) * G_SS + kb + lc];
                a[i][2] = sA[row * G_SS + kb + lc + 4];
                a[i][3] = sA[(row + 8) * G_SS + kb + lc + 4];
            }
#pragma unroll
            for (int j = 0; j < 4; j++) {
                int col = wn + j * 8 + lr;
                bfr[j][0] = sB[col * G_SS + kb + lc];
                bfr[j][1] = sB[col * G_SS + kb + lc + 4];
            }
#pragma unroll
            for (int i = 0; i < 2; i++)
#pragma unroll
                for (int j = 0; j < 4; j++)
                    mma_f16(c[i][j], a[i], bfr[j]);
        }
    }

#pragma unroll
    for (int i = 0; i < 2; i++) {
        int row0 = m0 + wm + i * 16 + lr;
#pragma unroll
        for (int j = 0; j < 4; j++) {
            int col = n0 + wn + j * 8 + (lc << 1);
            float b0 = d_bfused[col], b1 = d_bfused[col + 1];
            *(uint32_t*)&d_qkv[(size_t)row0 * NQKV + col] = pack2(c[i][j][0] + b0, c[i][j][1] + b1);
            *(uint32_t*)&d_qkv[(size_t)(row0 + 8) * NQKV + col] = pack2(c[i][j][2] + b0, c[i][j][3] + b1);
        }
    }
}

// ---------------- kernel 5: attention (fp16 mma, f32x2 conv) -----------------
// smem (float words):
//   [0,2176)     qc [n=64][17 f2] (d-pairs)   -> reused as pnm16 [64][36w]
//   [2176,4352)  kc [n=64][17 f2]
//   [4352,5504)  vdm16 [d=32][36w] (72 halves: m-major within row)
//   [5504,6784)  vmd16 [m=64][20w] (40 halves: d)
//   [6784,8064)  ond16 [n=64][20w]
//   [8064,8192)  rmaxP[64][2]
//   [8192,8320)  rsumP[64][2]
#define AT_KC   2176
#define AT_PNM  0
#define AT_VDM  4352
#define AT_VMD  5504
#define AT_OND  6784
#define AT_RMX  8064
#define AT_RSM  8192
#define AT_TOT  8320
__global__ void __launch_bounds__(256) attn_tc_kernel() {
    __shared__ __align__(16) float sh[AT_TOT];
    float2* qc2 = (float2*)sh;                           // [n][17 f2]
    float2* kc2 = (float2*)(sh + AT_KC);
    uint32_t* pnm16 = (uint32_t*)(sh + AT_PNM);          // [n][36 words]
    uint32_t* vdm16 = (uint32_t*)(sh + AT_VDM);          // [d][36 words]
    unsigned short* vdm16h = (unsigned short*)vdm16;     // [d][72 halves]
    uint32_t* vmd16 = (uint32_t*)(sh + AT_VMD);          // [m][20 words]
    uint32_t* ond16 = (uint32_t*)(sh + AT_OND);          // [n][20 words]
    float* rmaxP = sh + AT_RMX;
    float* rsumP = sh + AT_RSM;

    int w_   = blockIdx.x;
    int head = blockIdx.y;
    int t = threadIdx.x;

    int b   = w_ >> 8;
    int rem = w_ & 255;
    int wi  = rem >> 4, wj = rem & 15;
    int base_pix = b * HW + wi * 8 * WIMG + wj * 8;
    int chq = head * HD;

    // ---- phase 1: load q,k,v (fp16 global) ----
#pragma unroll
    for (int r = 0; r < 2; r++) {
        int idx = t + r * 256;             // 0..511
        int n  = idx >> 3;
        int dq = (idx & 7) << 2;           // 0,4,...,28
        int m = base_pix + ((n >> 3) * WIMG) + (n & 7);
        const unsigned short* p = d_qkv + (size_t)m * NQKV + chq + dq;
        uint2 qraw = *(const uint2*)p;
        uint2 kraw = *(const uint2*)(p + CIN);
        uint2 vraw = *(const uint2*)(p + 2 * CIN);
        float2 q01 = __half22float2(*reinterpret_cast<__half2*>(&qraw.x));
        float2 q23 = __half22float2(*reinterpret_cast<__half2*>(&qraw.y));
        float2 k01 = __half22float2(*reinterpret_cast<__half2*>(&kraw.x));
        float2 k23 = __half22float2(*reinterpret_cast<__half2*>(&kraw.y));
        int dp0 = dq >> 1;                 // d-pair index 0..14 (even)
        qc2[n * 17 + dp0]     = make_float2(q01.x * SCALE, q01.y * SCALE);
        qc2[n * 17 + dp0 + 1] = make_float2(q23.x * SCALE, q23.y * SCALE);
        kc2[n * 17 + dp0]     = make_float2(k01.x, k01.y);
        kc2[n * 17 + dp0 + 1] = make_float2(k23.x, k23.y);
        // v d-major halves
        const unsigned short* vh = (const unsigned short*)&vraw;
        vdm16h[(dq + 0) * 72 + n] = vh[0];
        vdm16h[(dq + 1) * 72 + n] = vh[1];
        vdm16h[(dq + 2) * 72 + n] = vh[2];
        vdm16h[(dq + 3) * 72 + n] = vh[3];
        // v m-major words (d pairs) — raw copy
        vmd16[n * 20 + (dq >> 1)]     = vraw.x;
        vmd16[n * 20 + (dq >> 1) + 1] = vraw.y;
    }
    __syncthreads();

    // ---- phase 2: 8x8 circular conv, packed f32x2 (2 channels/thread) ------
    // 128 threads: dp = t&15 (channel pair), ci = t>>4 (output row).
    // o[ci*8+j][2dp..2dp+1] = sum_{ai,aj} q[ai*8+aj] * k[ki*8+((j-aj)&7)], ki=(ci-ai)&7
    if (t < 128) {
        int dp = t & 15;
        int ci = t >> 4;   // 0..7 (warp w handles ci=w; q/k loads broadcast in-warp)
        const unsigned long long* qc = (const unsigned long long*)sh;
        const unsigned long long* kc = (const unsigned long long*)(sh + AT_KC);
        unsigned long long acc[8];
#pragma unroll
        for (int j = 0; j < 8; j++) acc[j] = 0ull;
#pragma unroll
        for (int ai = 0; ai < 8; ai++) {
            int ki = (ci - ai) & 7;
            unsigned long long qr[8], kr[8];
#pragma unroll
            for (int e = 0; e < 8; e++) qr[e] = qc[(ai * 8 + e) * 17 + dp];
#pragma unroll
            for (int e = 0; e < 8; e++) kr[e] = kc[(ki * 8 + e) * 17 + dp];
#pragma unroll
            for (int aj = 0; aj < 8; aj++)
#pragma unroll
                for (int j = 0; j < 8; j++)
                    fma2(acc[j], qr[aj], kr[(j - aj) & 7]);
        }
#pragma unroll
        for (int j = 0; j < 8; j++) {
            float fx, fy;
            asm("mov.b64 {%0, %1}, %2;" : "=f"(fx), "=f"(fy) : "l"(acc[j]));
            ond16[(ci * 8 + j) * 20 + dp] = pack2(fx, fy);
        }
    }
    __syncthreads();

    // ---- phase 3: logits s = o @ v^T + bias (fp16 mma, K=32 = 2 ksteps) ----
    int lane = t & 31, w = t >> 5;
    int wr = w >> 1, wc = w & 1;      // 4x2 warp grid
    int n0w = wr * 16;
    int lr = lane >> 2, lc = lane & 3;

    uint32_t afr[2][4];
#pragma unroll
    for (int ksv = 0; ksv < 2; ksv++) {
        int kb = ksv * 8;
        afr[ksv][0] = ond16[(n0w + lr) * 20 + kb + lc];
        afr[ksv][1] = ond16[(n0w + lr + 8) * 20 + kb + lc];
        afr[ksv][2] = ond16[(n0w + lr) * 20 + kb + lc + 4];
        afr[ksv][3] = ond16[(n0w + lr + 8) * 20 + kb + lc + 4];
    }
    int m0w = wc * 32;
    float sacc[4][4];
#pragma unroll
    for (int mt = 0; mt < 4; mt++)
#pragma unroll
        for (int q = 0; q < 4; q++) sacc[mt][q] = 0.f;
#pragma unroll
    for (int mt = 0; mt < 4; mt++) {
        int mrow = m0w + mt * 8 + lr;
#pragma unroll
        for (int ksv = 0; ksv < 2; ksv++) {
            int kb = ksv * 8;
            uint32_t bf[2] = {vmd16[mrow * 20 + kb + lc], vmd16[mrow * 20 + kb + lc + 4]};
            mma_f16(sacc[mt], afr[ksv], bf);
        }
    }
    // bias add
    {
        const float* bp = d_biasT + head * NWIN * NWIN;
#pragma unroll
        for (int mt = 0; mt < 4; mt++) {
            int col = m0w + mt * 8 + (lc << 1);
            float2 b0 = *(const float2*)(bp + (n0w + lr) * NWIN + col);
            float2 b1 = *(const float2*)(bp + (n0w + lr + 8) * NWIN + col);
            sacc[mt][0] += b0.x; sacc[mt][1] += b0.y;
            sacc[mt][2] += b1.x; sacc[mt][3] += b1.y;
        }
    }
    // softmax (2-warp combine over m)
    float mx0 = -1e30f, mx1 = -1e30f;
#pragma unroll
    for (int mt = 0; mt < 4; mt++) {
        mx0 = fmaxf(mx0, fmaxf(sacc[mt][0], sacc[mt][1]));
        mx1 = fmaxf(mx1, fmaxf(sacc[mt][2], sacc[mt][3]));
    }
    mx0 = fmaxf(mx0, __shfl_xor_sync(0xffffffffu, mx0, 1));
    mx0 = fmaxf(mx0, __shfl_xor_sync(0xffffffffu, mx0, 2));
    mx1 = fmaxf(mx1, __shfl_xor_sync(0xffffffffu, mx1, 1));
    mx1 = fmaxf(mx1, __shfl_xor_sync(0xffffffffu, mx1, 2));
    if (lc == 0) {
        rmaxP[(n0w + lr) * 2 + wc]     = mx0;
        rmaxP[(n0w + lr + 8) * 2 + wc] = mx1;
    }
    __syncthreads();
    float g0 = fmaxf(rmaxP[(n0w + lr) * 2],     rmaxP[(n0w + lr) * 2 + 1]);
    float g1 = fmaxf(rmaxP[(n0w + lr + 8) * 2], rmaxP[(n0w + lr + 8) * 2 + 1]);
    float s0 = 0.f, s1 = 0.f;
#pragma unroll
    for (int mt = 0; mt < 4; mt++) {
        float e0 = __expf(sacc[mt][0] - g0);
        float e1 = __expf(sacc[mt][1] - g0);
        float e2 = __expf(sacc[mt][2] - g1);
        float e3 = __expf(sacc[mt][3] - g1);
        s0 += e0 + e1; s1 += e2 + e3;
        int colw = wc * 16 + mt * 4 + lc;   // word index of m-pair
        pnm16[(n0w + lr) * 36 + colw]     = pack2(e0, e1);
        pnm16[(n0w + lr + 8) * 36 + colw] = pack2(e2, e3);
    }
    s0 += __shfl_xor_sync(0xffffffffu, s0, 1);
    s0 += __shfl_xor_sync(0xffffffffu, s0, 2);
    s1 += __shfl_xor_sync(0xffffffffu, s1, 1);
    s1 += __shfl_xor_sync(0xffffffffu, s1, 2);
    if (lc == 0) {
        rsumP[(n0w + lr) * 2 + wc]     = s0;
        rsumP[(n0w + lr + 8) * 2 + wc] = s1;
    }
    __syncthreads();

    // ---- phase 5: y = p @ v (fp16 mma, K=64 = 4 ksteps), normalize, store ---
    int d0w = wc * 16;
    float yacc[2][4];
#pragma unroll
    for (int dt = 0; dt < 2; dt++)
#pragma unroll
        for (int q = 0; q < 4; q++) yacc[dt][q] = 0.f;
#pragma unroll
    for (int st = 0; st < 4; st++) {
        int kb = st * 8;
        uint32_t a[4] = {
            pnm16[(n0w + lr) * 36 + kb + lc],
            pnm16[(n0w + lr + 8) * 36 + kb + lc],
            pnm16[(n0w + lr) * 36 + kb + lc + 4],
            pnm16[(n0w + lr + 8) * 36 + kb + lc + 4]};
#pragma unroll
        for (int dt = 0; dt < 2; dt++) {
            int dcol = d0w + dt * 8 + lr;
            uint32_t bf[2] = {vdm16[dcol * 36 + kb + lc], vdm16[dcol * 36 + kb + lc + 4]};
            mma_f16(yacc[dt], a, bf);
        }
    }
    {
        int r0 = n0w + lr, r1 = r0 + 8;
        float ri0 = 1.f / (rsumP[2 * r0] + rsumP[2 * r0 + 1]);
        float ri1 = 1.f / (rsumP[2 * r1] + rsumP[2 * r1 + 1]);
        int p0 = base_pix + ((r0 >> 3) * WIMG) + (r0 & 7);
        int p1 = base_pix + ((r1 >> 3) * WIMG) + (r1 & 7);
#pragma unroll
        for (int dt = 0; dt < 2; dt++) {
            int dc = chq + d0w + dt * 8 + (lc << 1);
            *(uint32_t*)&d_yb[(size_t)p0 * CIN + dc] = pack2(yacc[dt][0] * ri0, yacc[dt][1] * ri0);
            *(uint32_t*)&d_yb[(size_t)p1 * CIN + dc] = pack2(yacc[dt][2] * ri1, yacc[dt][3] * ri1);
        }
    }
}

// ---------------- kernel 6: GEMM2 out = yb @ pwh^T + pb ---------------------
__global__ void __launch_bounds__(256) gemm_proj_tc(const float* __restrict__ pb,
                                                    float* __restrict__ out) {
    __shared__ __align__(16) uint32_t sh[3 * G_SA_WORDS + 3 * G_SB_WORDS];  // 45 KB
    uint32_t* sAb = sh;
    uint32_t* sBb = sh + 3 * G_SA_WORDS;
    uint32_t sA_s = (uint32_t)__cvta_generic_to_shared(sAb);
    uint32_t sB_s = (uint32_t)__cvta_generic_to_shared(sBb);

    int m0 = blockIdx.y * 128;
    int n0 = blockIdx.x * 64;
    int b  = m0 >> 14;
    int hw0 = m0 & (HW - 1);

    int t = threadIdx.x;
    int lane = t & 31, warp = t >> 5;
    int wm = (warp >> 1) << 5, wn = (warp & 1) << 5;
    int lr = lane >> 2, lc = lane & 3;

    int a_m0 = t >> 2,         a_h0 = (t & 3) << 3;
    int a_m1 = (t + 256) >> 2, a_h1 = a_h0;
    int b_n = t >> 2,          b_h = (t & 3) << 3;

    float c[2][4][4];
#pragma unroll
    for (int i = 0; i < 2; i++)
#pragma unroll
        for (int j = 0; j < 4; j++)
#pragma unroll
            for (int q = 0; q < 4; q++) c[i][j][q] = 0.f;

#define G2L(stg, k0) do {                                                          \
        uint32_t dA = sA_s + ((stg) * G_SA_WORDS) * 4;                             \
        cp16(dA + (a_m0 * G_SS + (a_h0 >> 1)) * 4, d_yb + (size_t)(m0 + a_m0) * CIN + (k0) + a_h0); \
        cp16(dA + (a_m1 * G_SS + (a_h1 >> 1)) * 4, d_yb + (size_t)(m0 + a_m1) * CIN + (k0) + a_h1); \
        uint32_t dB = sB_s + ((stg) * G_SB_WORDS) * 4;                             \
        cp16(dB + (b_n * G_SS + (b_h >> 1)) * 4, d_pwh + (size_t)(n0 + b_n) * CIN + (k0) + b_h); \
    } while (0)

    G2L(0, 0);  CP_COMMIT();
    G2L(1, 32); CP_COMMIT();

    for (int it = 0; it < 6; it++) {
        CP_WAIT1();
        __syncthreads();
        int k0n = (it + 2) * 32;
        if (k0n < CIN) { G2L((it + 2) % 3, k0n); }
        CP_COMMIT();
        const uint32_t* sA = sAb + (it % 3) * G_SA_WORDS;
        const uint32_t* sB = sBb + (it % 3) * G_SB_WORDS;
#pragma unroll
        for (int ks = 0; ks < 2; ks++) {
            int kb = ks * 8;
            uint32_t a[2][4], bfr[4][2];
#pragma unroll
            for (int i = 0; i < 2; i++) {
                int row = wm + i * 16 + lr;
                a[i][0] = sA[row * G_SS + kb + lc];
                a[i][1] = sA[(row + 8) * G_SS + kb + lc];
                a[i][2] = sA[row * G_SS + kb + lc + 4];
                a[i][3] = sA[(row + 8) * G_SS + kb + lc + 4];
            }
#pragma unroll
            for (int j = 0; j < 4; j++) {
                int col = wn + j * 8 + lr;
                bfr[j][0] = sB[col * G_SS + kb + lc];
                bfr[j][1] = sB[col * G_SS + kb + lc + 4];
            }
#pragma unroll
            for (int i = 0; i < 2; i++)
#pragma unroll
                for (int j = 0; j < 4; j++)
                    mma_f16(c[i][j], a[i], bfr[j]);
        }
    }
    __syncthreads();

    // stage C in smem for coalesced transposed output
    float* Cs = (float*)sh;   // [128][65] = 8320 floats (33.3 KB <= 45 KB)
#pragma unroll
    for (int i = 0; i < 2; i++) {
        int row = wm + i * 16 + lr;
#pragma unroll
        for (int j = 0; j < 4; j++) {
            int col = wn + j * 8 + (lc << 1);
            Cs[row * 65 + col]           = c[i][j][0];
            Cs[row * 65 + col + 1]       = c[i][j][1];
            Cs[(row + 8) * 65 + col]     = c[i][j][2];
            Cs[(row + 8) * 65 + col + 1] = c[i][j][3];
        }
    }
    __syncthreads();

    int mL = t & 127;
    int nh = (t >> 7) << 5;
    for (int nn = 0; nn < 32; nn++) {
        int n = nh + nn;
        out[(size_t)(b * CIN + n0 + n) * HW + hw0 + mL] = Cs[mL * 65 + n] + pb[n0 + n];
    }
}

// ---------------- launch -----------------------------------------------------
extern "C" void kernel_launch(void* const* d_in, const int* in_sizes, int n_in,
                              void* d_out, int out_size) {
    const float* x      = (const float*)d_in[0];
    const float* V_w    = (const float*)d_in[1];
    const float* V_b    = (const float*)d_in[2];
    const float* QK_w   = (const float*)d_in[3];
    const float* QK_b   = (const float*)d_in[4];
    const float* proj_w = (const float*)d_in[5];
    const float* proj_b = (const float*)d_in[6];
    const float* mw1    = (const float*)d_in[7];
    const float* mb1    = (const float*)d_in[8];
    const float* mw2    = (const float*)d_in[9];
    const float* mb2    = (const float*)d_in[10];
    float* out = (float*)d_out;

    prep_w<<<(NQKV * CIN + 255) / 256, 256>>>(QK_w, QK_b, V_w, V_b, proj_w);
    bias_kernel<<<(NWIN * NWIN + 255) / 256, 256>>>(mw1, mb1, mw2, mb2);
    transpose_x<<<dim3(CIN / 32, MTOT / 32), 256>>>(x);
    gemm_qkv_tc<<<dim3(NQKV / 64, MTOT / 128), 256>>>();
    attn_tc_kernel<<<dim3(2048, NH), 256>>>();
    gemm_proj_tc<<<dim3(CIN / 64, MTOT / 128), 256>>>(proj_b, out);
}

// round 12
// speedup vs baseline: 1.1157x; 1.0278x over previous
#include <cuda_runtime.h>
#include <cuda_fp16.h>
#include <math.h>
#include <stdint.h>

// Problem constants
#define BATCH 8
#define CIN   192
#define HIMG  128
#define WIMG  128
#define HW    16384           // 128*128
#define MTOT  131072          // BATCH*HW
#define NQKV  576             // 3*C
#define NH    6
#define HD    32
#define WS    8
#define NWIN  64              // WS*WS
#define SCALE 0.17677669529663687f   // 32^-0.5

// ---------------- scratch (device globals; no runtime allocation) -----------
__device__ __align__(16) unsigned short d_xh [(size_t)MTOT * CIN];   // x^T fp16 [m][c]
__device__ __align__(16) unsigned short d_qkv[(size_t)MTOT * NQKV];  // fp16 [m][576]
__device__ __align__(16) unsigned short d_yb [(size_t)MTOT * CIN];   // fp16 [m][192]
__device__ __align__(16) unsigned short d_wfh[NQKV * CIN];           // fp16 [576][192]
__device__ __align__(16) unsigned short d_pwh[CIN * CIN];            // fp16 [192][192]
__device__ float d_bfused[NQKV];
__device__ float d_biasT[NH * NWIN * NWIN];      // [head][n][m]

// ---------------- helpers ----------------------------------------------------
__device__ __forceinline__ void mma_f16(float c[4], const uint32_t a[4], const uint32_t b[2]) {
    asm volatile(
        "mma.sync.aligned.m16n8k16.row.col.f32.f16.f16.f32 "
        "{%0,%1,%2,%3}, {%4,%5,%6,%7}, {%8,%9}, {%0,%1,%2,%3};"
        : "+f"(c[0]), "+f"(c[1]), "+f"(c[2]), "+f"(c[3])
        : "r"(a[0]), "r"(a[1]), "r"(a[2]), "r"(a[3]), "r"(b[0]), "r"(b[1]));
}
__device__ __forceinline__ uint32_t pack2(float a, float b) {
    __half2 h = __floats2half2_rn(a, b);
    return *reinterpret_cast<uint32_t*>(&h);
}
__device__ __forceinline__ void fma2(unsigned long long& acc, unsigned long long a,
                                     unsigned long long b) {
    asm("fma.rn.f32x2 %0, %1, %2, %0;" : "+l"(acc) : "l"(a), "l"(b));
}
__device__ __forceinline__ void cp16(uint32_t saddr, const void* g) {
    asm volatile("cp.async.cg.shared.global [%0], [%1], 16;" :: "r"(saddr), "l"(g));
}
#define CP_COMMIT() asm volatile("cp.async.commit_group;")
#define CP_WAIT1()  asm volatile("cp.async.wait_group 1;")

#define LDSM4(r, addr) \
    asm volatile("ldmatrix.sync.aligned.m8n8.x4.shared.b16 {%0,%1,%2,%3}, [%4];" \
                 : "=r"((r)[0]), "=r"((r)[1]), "=r"((r)[2]), "=r"((r)[3]) : "r"(addr))
#define LDSM2(r0, r1, addr) \
    asm volatile("ldmatrix.sync.aligned.m8n8.x2.shared.b16 {%0,%1}, [%2];" \
                 : "=r"(r0), "=r"(r1) : "r"(addr))

// ---------------- kernel 1: weight prep (fuse + fp16 convert) ---------------
__global__ void prep_w(const float* __restrict__ QK_w, const float* __restrict__ QK_b,
                       const float* __restrict__ V_w,  const float* __restrict__ V_b,
                       const float* __restrict__ pw) {
    int idx = blockIdx.x * 256 + threadIdx.x;
    if (idx < NQKV * CIN) {
        int n = idx / CIN, k = idx - n * CIN;
        float v = (n < 2 * CIN) ? QK_w[n * CIN + k] : V_w[(n - 2 * CIN) * CIN + k];
        d_wfh[idx] = __half_as_ushort(__float2half(v));
    }
    if (idx < CIN * CIN)
        d_pwh[idx] = __half_as_ushort(__float2half(pw[idx]));
    if (idx < NQKV)
        d_bfused[idx] = (idx < 2 * CIN) ? QK_b[idx] : V_b[idx - 2 * CIN];
}

// ---------------- kernel 2: relative-position bias via meta MLP -------------
__global__ void bias_kernel(const float* __restrict__ w1, const float* __restrict__ b1,
                            const float* __restrict__ w2, const float* __restrict__ b2) {
    int idx = blockIdx.x * 256 + threadIdx.x;   // 0..4095
    if (idx >= NWIN * NWIN) return;
    int n1 = idx >> 6, n2 = idx & 63;
    float di = (float)((n1 >> 3) - (n2 >> 3));
    float dj = (float)((n1 & 7) - (n2 & 7));
    float s0 = (di > 0.f) ? 1.f : ((di < 0.f) ? -1.f : 0.f);
    float s1 = (dj > 0.f) ? 1.f : ((dj < 0.f) ? -1.f : 0.f);
    float rp0 = s0 * log1pf(fabsf(di));
    float rp1 = s1 * log1pf(fabsf(dj));
    float acc[NH];
#pragma unroll
    for (int c = 0; c < NH; c++) acc[c] = b2[c];
    for (int t = 0; t < 256; t++) {
        float h = rp0 * w1[t] + rp1 * w1[256 + t] + b1[t];
        h = fmaxf(h, 0.f);
#pragma unroll
        for (int c = 0; c < NH; c++) acc[c] += h * w2[t * NH + c];
    }
#pragma unroll
    for (int c = 0; c < NH; c++)
        d_biasT[(c * NWIN + n1) * NWIN + n2] = acc[c];
}

// ---------------- kernel 3: transpose+convert x -> d_xh fp16 [m][c] ---------
__global__ void __launch_bounds__(256) transpose_x(const float* __restrict__ x) {
    __shared__ float tile[32][33];
    int cb = blockIdx.x << 5;
    int mb = blockIdx.y << 5;
    int b  = mb >> 14;
    int hw0 = mb & (HW - 1);
    int tx = threadIdx.x & 31, ty = threadIdx.x >> 5;
    const float* src = x + (size_t)b * CIN * HW + hw0;
#pragma unroll
    for (int i = 0; i < 4; i++)
        tile[ty + i * 8][tx] = src[(size_t)(cb + ty + i * 8) * HW + tx];
    __syncthreads();
#pragma unroll
    for (int i = 0; i < 4; i++) {
        int m = mb + ty + i * 8;
        d_xh[(size_t)m * CIN + cb + tx] =
            __half_as_ushort(__float2half(tile[tx][ty + i * 8]));
    }
}

// ---------------- GEMM common geometry ---------------------------------------
// fp16 m16n8k16, tiles 128x64, BK=32 halves (=16 half2 words), 3-stage cp.async
#define G_SS 20
#define G_SA_WORDS (128 * G_SS)      // 2560 words per stage
#define G_SB_WORDS (64 * G_SS)       // 1280 words per stage

// ---------------- kernel 4: GEMM1 qkv = xh @ wfh^T + b ----------------------
__global__ void __launch_bounds__(256) gemm_qkv_tc() {
    __shared__ __align__(16) uint32_t sh[3 * G_SA_WORDS + 3 * G_SB_WORDS];  // 45 KB
    uint32_t* sAb = sh;
    uint32_t* sBb = sh + 3 * G_SA_WORDS;
    uint32_t sA_s = (uint32_t)__cvta_generic_to_shared(sAb);
    uint32_t sB_s = (uint32_t)__cvta_generic_to_shared(sBb);

    int m0 = blockIdx.y * 128;
    int n0 = blockIdx.x * 64;
    int t = threadIdx.x;
    int lane = t & 31, warp = t >> 5;
    int wm = (warp >> 1) << 5, wn = (warp & 1) << 5;
    int lr = lane >> 2, lc = lane & 3;

    int a_m0 = t >> 2,         a_h0 = (t & 3) << 3;
    int a_m1 = (t + 256) >> 2, a_h1 = a_h0;
    int b_n = t >> 2,          b_h = (t & 3) << 3;

    // ldmatrix per-lane base addresses (bytes):
    // A x4: row = wm + (lane&15) (+i*16), word = kb + 4*(lane>>4)
    uint32_t aAddr = sA_s + (((wm + (lane & 15)) * G_SS + ((lane >> 4) << 2)) << 2);
    // B x2: row = wn + (lane&7) (+j*8), word = kb + 4*((lane>>3)&1)
    uint32_t bAddr = sB_s + (((wn + (lane & 7)) * G_SS + (((lane >> 3) & 1) << 2)) << 2);

    float c[2][4][4];
#pragma unroll
    for (int i = 0; i < 2; i++)
#pragma unroll
        for (int j = 0; j < 4; j++)
#pragma unroll
            for (int q = 0; q < 4; q++) c[i][j][q] = 0.f;

#define G1L(stg, k0) do {                                                          \
        uint32_t dA = sA_s + ((stg) * G_SA_WORDS) * 4;                             \
        cp16(dA + (a_m0 * G_SS + (a_h0 >> 1)) * 4, d_xh + (size_t)(m0 + a_m0) * CIN + (k0) + a_h0); \
        cp16(dA + (a_m1 * G_SS + (a_h1 >> 1)) * 4, d_xh + (size_t)(m0 + a_m1) * CIN + (k0) + a_h1); \
        uint32_t dB = sB_s + ((stg) * G_SB_WORDS) * 4;                             \
        cp16(dB + (b_n * G_SS + (b_h >> 1)) * 4, d_wfh + (size_t)(n0 + b_n) * CIN + (k0) + b_h); \
    } while (0)

    G1L(0, 0);  CP_COMMIT();
    G1L(1, 32); CP_COMMIT();

    for (int it = 0; it < 6; it++) {
        CP_WAIT1();
        __syncthreads();
        int k0n = (it + 2) * 32;
        if (k0n < CIN) { G1L((it + 2) % 3, k0n); }
        CP_COMMIT();
        uint32_t aSt = aAddr + (it % 3) * (G_SA_WORDS * 4);
        uint32_t bSt = bAddr + (it % 3) * (G_SB_WORDS * 4);
#pragma unroll
        for (int ks = 0; ks < 2; ks++) {
            int kbb = ks * 32;    // byte offset of k-word block
            uint32_t a[2][4], bfr[4][2];
#pragma unroll
            for (int i = 0; i < 2; i++)
                LDSM4(a[i], aSt + i * (16 * G_SS * 4) + kbb);
#pragma unroll
            for (int j = 0; j < 4; j++)
                LDSM2(bfr[j][0], bfr[j][1], bSt + j * (8 * G_SS * 4) + kbb);
#pragma unroll
            for (int i = 0; i < 2; i++)
#pragma unroll
                for (int j = 0; j < 4; j++)
                    mma_f16(c[i][j], a[i], bfr[j]);
        }
    }

#pragma unroll
    for (int i = 0; i < 2; i++) {
        int row0 = m0 + wm + i * 16 + lr;
#pragma unroll
        for (int j = 0; j < 4; j++) {
            int col = n0 + wn + j * 8 + (lc << 1);
            float b0 = d_bfused[col], b1 = d_bfused[col + 1];
            *(uint32_t*)&d_qkv[(size_t)row0 * NQKV + col] = pack2(c[i][j][0] + b0, c[i][j][1] + b1);
            *(uint32_t*)&d_qkv[(size_t)(row0 + 8) * NQKV + col] = pack2(c[i][j][2] + b0, c[i][j][3] + b1);
        }
    }
}

// ---------------- kernel 5: attention (fp16 mma, f32x2 conv) -----------------
#define AT_KC   2176
#define AT_PNM  0
#define AT_VDM  4352
#define AT_VMD  5504
#define AT_OND  6784
#define AT_RMX  8064
#define AT_RSM  8192
#define AT_TOT  8320
__global__ void __launch_bounds__(256) attn_tc_kernel() {
    __shared__ __align__(16) float sh[AT_TOT];
    float2* qc2 = (float2*)sh;                           // [n][17 f2]
    float2* kc2 = (float2*)(sh + AT_KC);
    uint32_t* pnm16 = (uint32_t*)(sh + AT_PNM);          // [n][36 words]
    uint32_t* vdm16 = (uint32_t*)(sh + AT_VDM);          // [d][36 words]
    unsigned short* vdm16h = (unsigned short*)vdm16;     // [d][72 halves]
    uint32_t* vmd16 = (uint32_t*)(sh + AT_VMD);          // [m][20 words]
    uint32_t* ond16 = (uint32_t*)(sh + AT_OND);          // [n][20 words]
    float* rmaxP = sh + AT_RMX;
    float* rsumP = sh + AT_RSM;

    int w_   = blockIdx.x;
    int head = blockIdx.y;
    int t = threadIdx.x;

    int b   = w_ >> 8;
    int rem = w_ & 255;
    int wi  = rem >> 4, wj = rem & 15;
    int base_pix = b * HW + wi * 8 * WIMG + wj * 8;
    int chq = head * HD;

    // ---- phase 1: load q,k,v (fp16 global) ----
#pragma unroll
    for (int r = 0; r < 2; r++) {
        int idx = t + r * 256;             // 0..511
        int n  = idx >> 3;
        int dq = (idx & 7) << 2;           // 0,4,...,28
        int m = base_pix + ((n >> 3) * WIMG) + (n & 7);
        const unsigned short* p = d_qkv + (size_t)m * NQKV + chq + dq;
        uint2 qraw = *(const uint2*)p;
        uint2 kraw = *(const uint2*)(p + CIN);
        uint2 vraw = *(const uint2*)(p + 2 * CIN);
        float2 q01 = __half22float2(*reinterpret_cast<__half2*>(&qraw.x));
        float2 q23 = __half22float2(*reinterpret_cast<__half2*>(&qraw.y));
        float2 k01 = __half22float2(*reinterpret_cast<__half2*>(&kraw.x));
        float2 k23 = __half22float2(*reinterpret_cast<__half2*>(&kraw.y));
        int dp0 = dq >> 1;                 // d-pair index (even)
        qc2[n * 17 + dp0]     = make_float2(q01.x * SCALE, q01.y * SCALE);
        qc2[n * 17 + dp0 + 1] = make_float2(q23.x * SCALE, q23.y * SCALE);
        kc2[n * 17 + dp0]     = make_float2(k01.x, k01.y);
        kc2[n * 17 + dp0 + 1] = make_float2(k23.x, k23.y);
        const unsigned short* vh = (const unsigned short*)&vraw;
        vdm16h[(dq + 0) * 72 + n] = vh[0];
        vdm16h[(dq + 1) * 72 + n] = vh[1];
        vdm16h[(dq + 2) * 72 + n] = vh[2];
        vdm16h[(dq + 3) * 72 + n] = vh[3];
        vmd16[n * 20 + (dq >> 1)]     = vraw.x;
        vmd16[n * 20 + (dq >> 1) + 1] = vraw.y;
    }
    __syncthreads();

    // ---- phase 2: 8x8 circular conv, packed f32x2 (2 channels/thread) ------
    if (t < 128) {
        int dp = t & 15;
        int ci = t >> 4;
        const unsigned long long* qc = (const unsigned long long*)sh;
        const unsigned long long* kc = (const unsigned long long*)(sh + AT_KC);
        unsigned long long acc[8];
#pragma unroll
        for (int j = 0; j < 8; j++) acc[j] = 0ull;
#pragma unroll
        for (int ai = 0; ai < 8; ai++) {
            int ki = (ci - ai) & 7;
            unsigned long long qr[8], kr[8];
#pragma unroll
            for (int e = 0; e < 8; e++) qr[e] = qc[(ai * 8 + e) * 17 + dp];
#pragma unroll
            for (int e = 0; e < 8; e++) kr[e] = kc[(ki * 8 + e) * 17 + dp];
#pragma unroll
            for (int aj = 0; aj < 8; aj++)
#pragma unroll
                for (int j = 0; j < 8; j++)
                    fma2(acc[j], qr[aj], kr[(j - aj) & 7]);
        }
#pragma unroll
        for (int j = 0; j < 8; j++) {
            float fx, fy;
            asm("mov.b64 {%0, %1}, %2;" : "=f"(fx), "=f"(fy) : "l"(acc[j]));
            ond16[(ci * 8 + j) * 20 + dp] = pack2(fx, fy);
        }
    }
    __syncthreads();

    // ---- phase 3: logits s = o @ v^T + bias (fp16 mma, K=32 = 2 ksteps) ----
    int lane = t & 31, w = t >> 5;
    int wr = w >> 1, wc = w & 1;      // 4x2 warp grid
    int n0w = wr * 16;
    int lr = lane >> 2, lc = lane & 3;

    uint32_t afr[2][4];
#pragma unroll
    for (int ksv = 0; ksv < 2; ksv++) {
        int kb = ksv * 8;
        afr[ksv][0] = ond16[(n0w + lr) * 20 + kb + lc];
        afr[ksv][1] = ond16[(n0w + lr + 8) * 20 + kb + lc];
        afr[ksv][2] = ond16[(n0w + lr) * 20 + kb + lc + 4];
        afr[ksv][3] = ond16[(n0w + lr + 8) * 20 + kb + lc + 4];
    }
    int m0w = wc * 32;
    float sacc[4][4];
#pragma unroll
    for (int mt = 0; mt < 4; mt++)
#pragma unroll
        for (int q = 0; q < 4; q++) sacc[mt][q] = 0.f;
#pragma unroll
    for (int mt = 0; mt < 4; mt++) {
        int mrow = m0w + mt * 8 + lr;
#pragma unroll
        for (int ksv = 0; ksv < 2; ksv++) {
            int kb = ksv * 8;
            uint32_t bf[2] = {vmd16[mrow * 20 + kb + lc], vmd16[mrow * 20 + kb + lc + 4]};
            mma_f16(sacc[mt], afr[ksv], bf);
        }
    }
    {
        const float* bp = d_biasT + head * NWIN * NWIN;
#pragma unroll
        for (int mt = 0; mt < 4; mt++) {
            int col = m0w + mt * 8 + (lc << 1);
            float2 b0 = *(const float2*)(bp + (n0w + lr) * NWIN + col);
            float2 b1 = *(const float2*)(bp + (n0w + lr + 8) * NWIN + col);
            sacc[mt][0] += b0.x; sacc[mt][1] += b0.y;
            sacc[mt][2] += b1.x; sacc[mt][3] += b1.y;
        }
    }
    float mx0 = -1e30f, mx1 = -1e30f;
#pragma unroll
    for (int mt = 0; mt < 4; mt++) {
        mx0 = fmaxf(mx0, fmaxf(sacc[mt][0], sacc[mt][1]));
        mx1 = fmaxf(mx1, fmaxf(sacc[mt][2], sacc[mt][3]));
    }
    mx0 = fmaxf(mx0, __shfl_xor_sync(0xffffffffu, mx0, 1));
    mx0 = fmaxf(mx0, __shfl_xor_sync(0xffffffffu, mx0, 2));
    mx1 = fmaxf(mx1, __shfl_xor_sync(0xffffffffu, mx1, 1));
    mx1 = fmaxf(mx1, __shfl_xor_sync(0xffffffffu, mx1, 2));
    if (lc == 0) {
        rmaxP[(n0w + lr) * 2 + wc]     = mx0;
        rmaxP[(n0w + lr + 8) * 2 + wc] = mx1;
    }
    __syncthreads();
    float g0 = fmaxf(rmaxP[(n0w + lr) * 2],     rmaxP[(n0w + lr) * 2 + 1]);
    float g1 = fmaxf(rmaxP[(n0w + lr + 8) * 2], rmaxP[(n0w + lr + 8) * 2 + 1]);
    float s0 = 0.f, s1 = 0.f;
#pragma unroll
    for (int mt = 0; mt < 4; mt++) {
        float e0 = __expf(sacc[mt][0] - g0);
        float e1 = __expf(sacc[mt][1] - g0);
        float e2 = __expf(sacc[mt][2] - g1);
        float e3 = __expf(sacc[mt][3] - g1);
        s0 += e0 + e1; s1 += e2 + e3;
        int colw = wc * 16 + mt * 4 + lc;   // word index of m-pair
        pnm16[(n0w + lr) * 36 + colw]     = pack2(e0, e1);
        pnm16[(n0w + lr + 8) * 36 + colw] = pack2(e2, e3);
    }
    s0 += __shfl_xor_sync(0xffffffffu, s0, 1);
    s0 += __shfl_xor_sync(0xffffffffu, s0, 2);
    s1 += __shfl_xor_sync(0xffffffffu, s1, 1);
    s1 += __shfl_xor_sync(0xffffffffu, s1, 2);
    if (lc == 0) {
        rsumP[(n0w + lr) * 2 + wc]     = s0;
        rsumP[(n0w + lr + 8) * 2 + wc] = s1;
    }
    __syncthreads();

    // ---- phase 5: y = p @ v (fp16 mma, K=64 = 4 ksteps), normalize, store ---
    int d0w = wc * 16;
    float yacc[2][4];
#pragma unroll
    for (int dt = 0; dt < 2; dt++)
#pragma unroll
        for (int q = 0; q < 4; q++) yacc[dt][q] = 0.f;
#pragma unroll
    for (int st = 0; st < 4; st++) {
        int kb = st * 8;
        uint32_t a[4] = {
            pnm16[(n0w + lr) * 36 + kb + lc],
            pnm16[(n0w + lr + 8) * 36 + kb + lc],
            pnm16[(n0w + lr) * 36 + kb + lc + 4],
            pnm16[(n0w + lr + 8) * 36 + kb + lc + 4]};
#pragma unroll
        for (int dt = 0; dt < 2; dt++) {
            int dcol = d0w + dt * 8 + lr;
            uint32_t bf[2] = {vdm16[dcol * 36 + kb + lc], vdm16[dcol * 36 + kb + lc + 4]};
            mma_f16(yacc[dt], a, bf);
        }
    }
    {
        int r0 = n0w + lr, r1 = r0 + 8;
        float ri0 = 1.f / (rsumP[2 * r0] + rsumP[2 * r0 + 1]);
        float ri1 = 1.f / (rsumP[2 * r1] + rsumP[2 * r1 + 1]);
        int p0 = base_pix + ((r0 >> 3) * WIMG) + (r0 & 7);
        int p1 = base_pix + ((r1 >> 3) * WIMG) + (r1 & 7);
#pragma unroll
        for (int dt = 0; dt < 2; dt++) {
            int dc = chq + d0w + dt * 8 + (lc << 1);
            *(uint32_t*)&d_yb[(size_t)p0 * CIN + dc] = pack2(yacc[dt][0] * ri0, yacc[dt][1] * ri0);
            *(uint32_t*)&d_yb[(size_t)p1 * CIN + dc] = pack2(yacc[dt][2] * ri1, yacc[dt][3] * ri1);
        }
    }
}

// ---------------- kernel 6: GEMM2 out = yb @ pwh^T + pb ---------------------
__global__ void __launch_bounds__(256) gemm_proj_tc(const float* __restrict__ pb,
                                                    float* __restrict__ out) {
    __shared__ __align__(16) uint32_t sh[3 * G_SA_WORDS + 3 * G_SB_WORDS];  // 45 KB
    uint32_t* sAb = sh;
    uint32_t* sBb = sh + 3 * G_SA_WORDS;
    uint32_t sA_s = (uint32_t)__cvta_generic_to_shared(sAb);
    uint32_t sB_s = (uint32_t)__cvta_generic_to_shared(sBb);

    int m0 = blockIdx.y * 128;
    int n0 = blockIdx.x * 64;
    int b  = m0 >> 14;
    int hw0 = m0 & (HW - 1);

    int t = threadIdx.x;
    int lane = t & 31, warp = t >> 5;
    int wm = (warp >> 1) << 5, wn = (warp & 1) << 5;
    int lr = lane >> 2, lc = lane & 3;

    int a_m0 = t >> 2,         a_h0 = (t & 3) << 3;
    int a_m1 = (t + 256) >> 2, a_h1 = a_h0;
    int b_n = t >> 2,          b_h = (t & 3) << 3;

    uint32_t aAddr = sA_s + (((wm + (lane & 15)) * G_SS + ((lane >> 4) << 2)) << 2);
    uint32_t bAddr = sB_s + (((wn + (lane & 7)) * G_SS + (((lane >> 3) & 1) << 2)) << 2);

    float c[2][4][4];
#pragma unroll
    for (int i = 0; i < 2; i++)
#pragma unroll
        for (int j = 0; j < 4; j++)
#pragma unroll
            for (int q = 0; q < 4; q++) c[i][j][q] = 0.f;

#define G2L(stg, k0) do {                                                          \
        uint32_t dA = sA_s + ((stg) * G_SA_WORDS) * 4;                             \
        cp16(dA + (a_m0 * G_SS + (a_h0 >> 1)) * 4, d_yb + (size_t)(m0 + a_m0) * CIN + (k0) + a_h0); \
        cp16(dA + (a_m1 * G_SS + (a_h1 >> 1)) * 4, d_yb + (size_t)(m0 + a_m1) * CIN + (k0) + a_h1); \
        uint32_t dB = sB_s + ((stg) * G_SB_WORDS) * 4;                             \
        cp16(dB + (b_n * G_SS + (b_h >> 1)) * 4, d_pwh + (size_t)(n0 + b_n) * CIN + (k0) + b_h); \
    } while (0)

    G2L(0, 0);  CP_COMMIT();
    G2L(1, 32); CP_COMMIT();

    for (int it = 0; it < 6; it++) {
        CP_WAIT1();
        __syncthreads();
        int k0n = (it + 2) * 32;
        if (k0n < CIN) { G2L((it + 2) % 3, k0n); }
        CP_COMMIT();
        uint32_t aSt = aAddr + (it % 3) * (G_SA_WORDS * 4);
        uint32_t bSt = bAddr + (it % 3) * (G_SB_WORDS * 4);
#pragma unroll
        for (int ks = 0; ks < 2; ks++) {
            int kbb = ks * 32;
            uint32_t a[2][4], bfr[4][2];
#pragma unroll
            for (int i = 0; i < 2; i++)
                LDSM4(a[i], aSt + i * (16 * G_SS * 4) + kbb);
#pragma unroll
            for (int j = 0; j < 4; j++)
                LDSM2(bfr[j][0], bfr[j][1], bSt + j * (8 * G_SS * 4) + kbb);
#pragma unroll
            for (int i = 0; i < 2; i++)
#pragma unroll
                for (int j = 0; j < 4; j++)
                    mma_f16(c[i][j], a[i], bfr[j]);
        }
    }
    __syncthreads();

    // stage C in smem for coalesced transposed output
    float* Cs = (float*)sh;   // [128][65]
#pragma unroll
    for (int i = 0; i < 2; i++) {
        int row = wm + i * 16 + lr;
#pragma unroll
        for (int j = 0; j < 4; j++) {
            int col = wn + j * 8 + (lc << 1);
            Cs[row * 65 + col]           = c[i][j][0];
            Cs[row * 65 + col + 1]       = c[i][j][1];
            Cs[(row + 8) * 65 + col]     = c[i][j][2];
            Cs[(row + 8) * 65 + col + 1] = c[i][j][3];
        }
    }
    __syncthreads();

    int mL = t & 127;
    int nh = (t >> 7) << 5;
    for (int nn = 0; nn < 32; nn++) {
        int n = nh + nn;
        out[(size_t)(b * CIN + n0 + n) * HW + hw0 + mL] = Cs[mL * 65 + n] + pb[n0 + n];
    }
}

// ---------------- launch -----------------------------------------------------
extern "C" void kernel_launch(void* const* d_in, const int* in_sizes, int n_in,
                              void* d_out, int out_size) {
    const float* x      = (const float*)d_in[0];
    const float* V_w    = (const float*)d_in[1];
    const float* V_b    = (const float*)d_in[2];
    const float* QK_w   = (const float*)d_in[3];
    const float* QK_b   = (const float*)d_in[4];
    const float* proj_w = (const float*)d_in[5];
    const float* proj_b = (const float*)d_in[6];
    const float* mw1    = (const float*)d_in[7];
    const float* mb1    = (const float*)d_in[8];
    const float* mw2    = (const float*)d_in[9];
    const float* mb2    = (const float*)d_in[10];
    float* out = (float*)d_out;

    prep_w<<<(NQKV * CIN + 255) / 256, 256>>>(QK_w, QK_b, V_w, V_b, proj_w);
    bias_kernel<<<(NWIN * NWIN + 255) / 256, 256>>>(mw1, mb1, mw2, mb2);
    transpose_x<<<dim3(CIN / 32, MTOT / 32), 256>>>(x);
    gemm_qkv_tc<<<dim3(NQKV / 64, MTOT / 128), 256>>>();
    attn_tc_kernel<<<dim3(2048, NH), 256>>>();
    gemm_proj_tc<<<dim3(CIN / 64, MTOT / 128), 256>>>(proj_b, out);
}